// round 14
// baseline (speedup 1.0000x reference)
#include <cuda_runtime.h>
#include <cuda_bf16.h>

#define B_SZ 32
#define F_SZ 257
#define T_SZ 3000
#define T4_SZ 750                 // float4 per row
#define NCHUNK 8
#define FCHUNK 33                 // 7*33 = 231, last chunk = 26 rows
#define NXT 3                     // t4 tiles of 256
#define THREADS 256
#define NB1 (NXT * NCHUNK * B_SZ) // 768 colsum blocks
#define MOMENTUM 0.99f
#define ONE_MINUS_M 0.01f
#define EPS 1e-8f
#define SEG 12                    // 256*12 = 3072 >= 3000

// Scratch (static device globals; zero-initialized at load).
// g_fm is accumulated via RED atomics and re-zeroed by its consumer.
__device__ float g_fm[B_SZ * T_SZ];
__device__ __align__(16) float g_inv[B_SZ * T_SZ];
__device__ int g_cnt1[B_SZ];      // colsum-block arrivals per batch (self-reset)

// ---------------------------------------------------------------------------
// kA: column sums accumulated straight into g_fm with RED.ADD; last-arriving
// block per batch runs the EMA scan from g_fm (12 KB) and re-zeroes it.
// grid: (NXT, NCHUNK, B_SZ) = 768 blocks, 256 threads.
// ---------------------------------------------------------------------------
__global__ __launch_bounds__(THREADS)
void ema_kA(const float* __restrict__ mag,
            const float* __restrict__ bias,
            const float* __restrict__ running_mean,
            float* __restrict__ out_mean) {
    __shared__ float s_buf[2 * T_SZ];
    __shared__ float sA[THREADS], sB[THREADS];
    __shared__ int s_last;

    const int tid = threadIdx.x;
    const int xt  = blockIdx.x;
    const int ch  = blockIdx.y;
    const int b   = blockIdx.z;
    const int t4  = xt * THREADS + tid;

    // ---------------- phase 1: column sums, RED into g_fm ------------------
    if (t4 < T4_SZ) {
        int f0 = ch * FCHUNK;
        int f1 = f0 + FCHUNK;
        if (f1 > F_SZ) f1 = F_SZ;

        const float4* base = reinterpret_cast<const float4*>(mag)
                           + (size_t)b * F_SZ * T4_SZ + t4;

        float4 s = make_float4(0.f, 0.f, 0.f, 0.f);
        int f = f0;
        #pragma unroll 1
        for (; f + 8 <= f1; f += 8) {
            float4 v0 = base[(size_t)(f + 0) * T4_SZ];
            float4 v1 = base[(size_t)(f + 1) * T4_SZ];
            float4 v2 = base[(size_t)(f + 2) * T4_SZ];
            float4 v3 = base[(size_t)(f + 3) * T4_SZ];
            float4 v4 = base[(size_t)(f + 4) * T4_SZ];
            float4 v5 = base[(size_t)(f + 5) * T4_SZ];
            float4 v6 = base[(size_t)(f + 6) * T4_SZ];
            float4 v7 = base[(size_t)(f + 7) * T4_SZ];
            s.x += ((v0.x + v1.x) + (v2.x + v3.x)) + ((v4.x + v5.x) + (v6.x + v7.x));
            s.y += ((v0.y + v1.y) + (v2.y + v3.y)) + ((v4.y + v5.y) + (v6.y + v7.y));
            s.z += ((v0.z + v1.z) + (v2.z + v3.z)) + ((v4.z + v5.z) + (v6.z + v7.z));
            s.w += ((v0.w + v1.w) + (v2.w + v3.w)) + ((v4.w + v5.w) + (v6.w + v7.w));
        }
        for (; f < f1; f++) {
            float4 v = base[(size_t)f * T4_SZ];
            s.x += v.x; s.y += v.y; s.z += v.z; s.w += v.w;
        }

        float* dst = g_fm + (size_t)b * T_SZ + 4 * t4;
        atomicAdd(dst + 0, s.x);            // unused return -> RED.ADD
        atomicAdd(dst + 1, s.y);
        atomicAdd(dst + 2, s.z);
        atomicAdd(dst + 3, s.w);
    }

    __threadfence();            // release RED contributions
    __syncthreads();
    if (tid == 0)
        s_last = (atomicAdd(&g_cnt1[b], 1) == NXT * NCHUNK - 1);
    __syncthreads();
    if (!s_last) return;

    // ---------------- phase 2: per-batch EMA scan from g_fm ----------------
    for (int t = tid; t < T_SZ; t += THREADS)
        s_buf[t] = __ldcg(&g_fm[(size_t)b * T_SZ + t]) * (1.0f / (float)F_SZ);
    __syncthreads();

    float x[SEG];
    float A = 1.0f, Bc = 0.0f;
    const int t0 = tid * SEG;
    #pragma unroll
    for (int j = 0; j < SEG; j++) {
        int t = t0 + j;
        if (t < T_SZ) {
            float fm = s_buf[t];
            x[j] = fm;
            A  *= MOMENTUM;
            Bc  = MOMENTUM * Bc + ONE_MINUS_M * fm;
        }
    }
    __syncthreads();

    sA[tid] = A; sB[tid] = Bc;
    __syncthreads();
    #pragma unroll
    for (int off = 1; off < THREADS; off <<= 1) {
        float a2 = sA[tid], b2 = sB[tid];
        float a1 = 1.0f, b1 = 0.0f;
        if (tid >= off) { a1 = sA[tid - off]; b1 = sB[tid - off]; }
        __syncthreads();
        sA[tid] = a2 * a1;
        sB[tid] = a2 * b1 + b2;
        __syncthreads();
    }

    float Ap = 1.0f, Bp = 0.0f;
    if (tid > 0) { Ap = sA[tid - 1]; Bp = sB[tid - 1]; }

    float m = Ap * running_mean[0] + Bp;
    const float bi = bias[0];

    #pragma unroll
    for (int j = 0; j < SEG; j++) {
        int t = t0 + j;
        if (t < T_SZ) {
            m = MOMENTUM * m + ONE_MINUS_M * x[j];
            float mwb = m + bi;
            s_buf[t]        = 1.0f / (mwb + EPS);
            s_buf[T_SZ + t] = mwb;
        }
    }
    __syncthreads();

    float* invp  = g_inv + (size_t)b * T_SZ;
    float* meanp = out_mean + (size_t)b * T_SZ;
    for (int t = tid; t < T_SZ; t += THREADS) {
        invp[t]  = s_buf[t];
        meanp[t] = s_buf[T_SZ + t];
        g_fm[(size_t)b * T_SZ + t] = 0.0f;   // re-zero for next replay
    }
    __syncthreads();
    if (tid == 0) atomicExch(&g_cnt1[b], 0); // replay-safe reset
}

// ---------------------------------------------------------------------------
// kB: mag_norm = mag * inv[b,t]; 4 f-rows per iv load; reverse-b for L2
// freshness; evict-first streaming stores.  (R11 measured-best version.)
// grid: (3, 65, 32), block 256.
// ---------------------------------------------------------------------------
__global__ __launch_bounds__(256)
void ema_kB(const float* __restrict__ mag,
            float* __restrict__ out_norm) {
    int t4 = blockIdx.x * blockDim.x + threadIdx.x;
    if (t4 >= T4_SZ) return;
    int f0 = blockIdx.y * 4;                 // 0,4,...,256
    int b  = (B_SZ - 1) - blockIdx.z;

    float4 iv = __ldca(reinterpret_cast<const float4*>(g_inv) + (size_t)b * T4_SZ + t4);

    const int nrows = (F_SZ - f0) < 4 ? (F_SZ - f0) : 4;
    size_t idx0 = ((size_t)b * F_SZ + f0) * T4_SZ + t4;

    float4 v[4];
    #pragma unroll
    for (int r = 0; r < 4; r++)
        if (r < nrows) v[r] = reinterpret_cast<const float4*>(mag)[idx0 + (size_t)r * T4_SZ];

    #pragma unroll
    for (int r = 0; r < 4; r++) {
        if (r < nrows) {
            v[r].x *= iv.x; v[r].y *= iv.y; v[r].z *= iv.z; v[r].w *= iv.w;
            __stcs(reinterpret_cast<float4*>(out_norm) + idx0 + (size_t)r * T4_SZ, v[r]);
        }
    }
}

// ---------------------------------------------------------------------------
extern "C" void kernel_launch(void* const* d_in, const int* in_sizes, int n_in,
                              void* d_out, int out_size) {
    const float* mag          = (const float*)d_in[0];
    const float* bias         = (const float*)d_in[1];
    const float* running_mean = (const float*)d_in[2];
    float* out = (float*)d_out;

    float* out_norm = out;                                // [B, F, T]
    float* out_mean = out + (size_t)B_SZ * F_SZ * T_SZ;   // [B, 1, T]

    {
        dim3 grid(NXT, NCHUNK, B_SZ);
        ema_kA<<<grid, THREADS>>>(mag, bias, running_mean, out_mean);
    }
    {
        dim3 grid(3, (F_SZ + 3) / 4, B_SZ);
        ema_kB<<<grid, 256>>>(mag, out_norm);
    }
}

// round 15
// speedup vs baseline: 1.1495x; 1.1495x over previous
#include <cuda_runtime.h>
#include <cuda_bf16.h>

#define B_SZ 32
#define F_SZ 257
#define T_SZ 3000
#define T4_SZ 750                 // float4 per row
#define NCHUNK 8                  // F-chunks: 7x32 + 33
#define NXT 3                     // t4 tiles of 256
#define THREADS 256
#define NB1 (NXT * NCHUNK * B_SZ) // 768 colsum blocks
#define MOMENTUM 0.99f
#define ONE_MINUS_M 0.01f
#define EPS 1e-8f
#define SEG 12                    // 256*12 = 3072 >= 3000

// Scratch (static device globals; zero-initialized at load)
__device__ __align__(16) float g_part[NCHUNK * B_SZ * T_SZ];
__device__ __align__(16) float g_inv[B_SZ * T_SZ];
__device__ int g_cnt1[B_SZ];      // colsum-block arrivals per batch (self-reset)

// ---------------------------------------------------------------------------
// kA: column sums; last-arriving block per batch folds reduce + EMA scan.
// grid: 768 blocks (b slowest), 256 threads.
// ---------------------------------------------------------------------------
__global__ __launch_bounds__(THREADS)
void ema_kA(const float* __restrict__ mag,
            const float* __restrict__ bias,
            const float* __restrict__ running_mean,
            float* __restrict__ out_mean) {
    __shared__ float s_buf[2 * T_SZ];
    __shared__ float sA[THREADS], sB[THREADS];
    __shared__ int s_last;

    const int bid = blockIdx.x;
    const int tid = threadIdx.x;
    const int b   = bid / (NXT * NCHUNK);          // slowest: batch
    const int rem = bid % (NXT * NCHUNK);
    const int ch  = rem / NXT;
    const int xt  = rem % NXT;
    const int t4  = xt * THREADS + tid;

    if (t4 < T4_SZ) {
        // chunks 0..6: 32 rows; chunk 7: 33 rows (224..257)
        int f0 = ch * 32;
        int f1 = (ch == NCHUNK - 1) ? F_SZ : f0 + 32;

        const float4* base = reinterpret_cast<const float4*>(mag)
                           + (size_t)b * F_SZ * T4_SZ + t4;

        float4 s = make_float4(0.f, 0.f, 0.f, 0.f);
        int f = f0;
        #pragma unroll 1
        for (; f + 8 <= f1; f += 8) {
            float4 v0 = base[(size_t)(f + 0) * T4_SZ];
            float4 v1 = base[(size_t)(f + 1) * T4_SZ];
            float4 v2 = base[(size_t)(f + 2) * T4_SZ];
            float4 v3 = base[(size_t)(f + 3) * T4_SZ];
            float4 v4 = base[(size_t)(f + 4) * T4_SZ];
            float4 v5 = base[(size_t)(f + 5) * T4_SZ];
            float4 v6 = base[(size_t)(f + 6) * T4_SZ];
            float4 v7 = base[(size_t)(f + 7) * T4_SZ];
            s.x += ((v0.x + v1.x) + (v2.x + v3.x)) + ((v4.x + v5.x) + (v6.x + v7.x));
            s.y += ((v0.y + v1.y) + (v2.y + v3.y)) + ((v4.y + v5.y) + (v6.y + v7.y));
            s.z += ((v0.z + v1.z) + (v2.z + v3.z)) + ((v4.z + v5.z) + (v6.z + v7.z));
            s.w += ((v0.w + v1.w) + (v2.w + v3.w)) + ((v4.w + v5.w) + (v6.w + v7.w));
        }
        for (; f < f1; f++) {
            float4 v = base[(size_t)f * T4_SZ];
            s.x += v.x; s.y += v.y; s.z += v.z; s.w += v.w;
        }
        reinterpret_cast<float4*>(g_part)[((size_t)ch * B_SZ + b) * T4_SZ + t4] = s;
    }

    __threadfence();            // release partial writes
    __syncthreads();
    if (tid == 0)
        s_last = (atomicAdd(&g_cnt1[b], 1) == NXT * NCHUNK - 1);
    __syncthreads();
    if (!s_last) return;

    // ---- last block of batch b: reduce partials + full EMA scan ----------
    for (int t = tid; t < T_SZ; t += THREADS) {
        float acc = 0.f;
        #pragma unroll
        for (int c = 0; c < NCHUNK; c++)
            acc += __ldcg(&g_part[((size_t)c * B_SZ + b) * T_SZ + t]);
        s_buf[t] = acc * (1.0f / (float)F_SZ);
    }
    __syncthreads();

    float x[SEG];
    float A = 1.0f, Bc = 0.0f;
    const int t0 = tid * SEG;
    #pragma unroll
    for (int j = 0; j < SEG; j++) {
        int t = t0 + j;
        if (t < T_SZ) {
            float fm = s_buf[t];
            x[j] = fm;
            A  *= MOMENTUM;
            Bc  = MOMENTUM * Bc + ONE_MINUS_M * fm;
        }
    }
    __syncthreads();

    sA[tid] = A; sB[tid] = Bc;
    __syncthreads();
    #pragma unroll
    for (int off = 1; off < THREADS; off <<= 1) {
        float a2 = sA[tid], b2 = sB[tid];
        float a1 = 1.0f, b1 = 0.0f;
        if (tid >= off) { a1 = sA[tid - off]; b1 = sB[tid - off]; }
        __syncthreads();
        sA[tid] = a2 * a1;
        sB[tid] = a2 * b1 + b2;
        __syncthreads();
    }

    float Ap = 1.0f, Bp = 0.0f;
    if (tid > 0) { Ap = sA[tid - 1]; Bp = sB[tid - 1]; }

    float m = Ap * running_mean[0] + Bp;
    const float bi = bias[0];

    #pragma unroll
    for (int j = 0; j < SEG; j++) {
        int t = t0 + j;
        if (t < T_SZ) {
            m = MOMENTUM * m + ONE_MINUS_M * x[j];
            float mwb = m + bi;
            s_buf[t]        = 1.0f / (mwb + EPS);
            s_buf[T_SZ + t] = mwb;
        }
    }
    __syncthreads();

    float* invp  = g_inv + (size_t)b * T_SZ;
    float* meanp = out_mean + (size_t)b * T_SZ;
    for (int t = tid; t < T_SZ; t += THREADS) {
        invp[t]  = s_buf[t];
        meanp[t] = s_buf[T_SZ + t];
    }
    __syncthreads();
    if (tid == 0) atomicExch(&g_cnt1[b], 0);   // replay-safe reset
}

// ---------------------------------------------------------------------------
// kB: mag_norm = mag * inv[b,t]; 4 f-rows per iv load; reverse-b for L2
// freshness; WRITE-THROUGH stores so out_norm doesn't evict L2-resident mag.
// grid: (3, 65, 32), block 256.
// ---------------------------------------------------------------------------
__global__ __launch_bounds__(256)
void ema_kB(const float* __restrict__ mag,
            float* __restrict__ out_norm) {
    int t4 = blockIdx.x * blockDim.x + threadIdx.x;
    if (t4 >= T4_SZ) return;
    int f0 = blockIdx.y * 4;                 // 0,4,...,256
    int b  = (B_SZ - 1) - blockIdx.z;

    float4 iv = __ldca(reinterpret_cast<const float4*>(g_inv) + (size_t)b * T4_SZ + t4);

    const int nrows = (F_SZ - f0) < 4 ? (F_SZ - f0) : 4;
    size_t idx0 = ((size_t)b * F_SZ + f0) * T4_SZ + t4;

    float4 v[4];
    #pragma unroll
    for (int r = 0; r < 4; r++)
        if (r < nrows) v[r] = reinterpret_cast<const float4*>(mag)[idx0 + (size_t)r * T4_SZ];

    #pragma unroll
    for (int r = 0; r < 4; r++) {
        if (r < nrows) {
            v[r].x *= iv.x; v[r].y *= iv.y; v[r].z *= iv.z; v[r].w *= iv.w;
            __stwt(reinterpret_cast<float4*>(out_norm) + idx0 + (size_t)r * T4_SZ, v[r]);
        }
    }
}

// ---------------------------------------------------------------------------
extern "C" void kernel_launch(void* const* d_in, const int* in_sizes, int n_in,
                              void* d_out, int out_size) {
    const float* mag          = (const float*)d_in[0];
    const float* bias         = (const float*)d_in[1];
    const float* running_mean = (const float*)d_in[2];
    float* out = (float*)d_out;

    float* out_norm = out;                                // [B, F, T]
    float* out_mean = out + (size_t)B_SZ * F_SZ * T_SZ;   // [B, 1, T]

    ema_kA<<<NB1, THREADS>>>(mag, bias, running_mean, out_mean);
    {
        dim3 grid(3, (F_SZ + 3) / 4, B_SZ);
        ema_kB<<<grid, 256>>>(mag, out_norm);
    }
}

// round 16
// speedup vs baseline: 1.1705x; 1.0183x over previous
#include <cuda_runtime.h>
#include <cuda_bf16.h>

#define B_SZ 32
#define F_SZ 257
#define T_SZ 3000
#define T4_SZ 750                 // float4 per row
#define NCHUNK 8                  // F-chunks: 7x32 + 33
#define NXT 3                     // t4 tiles of 256 -> t segments of 1024
#define THREADS 256
#define SEGT 1024                 // t per segment (last: 952)
#define MOMENTUM 0.99f
#define ONE_MINUS_M 0.01f
#define EPS 1e-8f
#define SEG2 4                    // 256*4 = 1024

// Scratch (static device globals; zero-initialized at load)
__device__ __align__(16) float g_part[NCHUNK * B_SZ * T_SZ];
__device__ __align__(16) float g_inv[B_SZ * T_SZ];
__device__ float g_mval[B_SZ * NXT];     // segment-exit EMA state
__device__ int   g_mflag[B_SZ * NXT];    // handoff flags (self-reset)
__device__ int   g_cnt[B_SZ * NXT];      // chunk arrivals per (b,xt) (self-reset)

// ---------------------------------------------------------------------------
// kA: column sums; last-arriver per (b, xt) becomes the segment scanner:
// fold 8 partials for its 1024-t range, local pair-scan, scalar chain across
// xt, then parallel inv/mean writeback.
// grid: (NXT, NCHUNK, B_SZ) = 768 blocks, 256 threads.
// ---------------------------------------------------------------------------
__global__ __launch_bounds__(THREADS)
void ema_kA(const float* __restrict__ mag,
            const float* __restrict__ bias,
            const float* __restrict__ running_mean,
            float* __restrict__ out_mean) {
    __shared__ float s_stage[2 * SEGT];     // x, then inv|mean
    __shared__ float sA[THREADS], sB[THREADS];
    __shared__ int s_last;
    __shared__ float s_min;

    const int tid = threadIdx.x;
    const int xt  = blockIdx.x;
    const int ch  = blockIdx.y;
    const int b   = blockIdx.z;
    const int t4  = xt * THREADS + tid;

    // ---------------- phase 1: column sums for (b, ch, xt) -----------------
    if (t4 < T4_SZ) {
        int f0 = ch * 32;
        int f1 = (ch == NCHUNK - 1) ? F_SZ : f0 + 32;

        const float4* base = reinterpret_cast<const float4*>(mag)
                           + (size_t)b * F_SZ * T4_SZ + t4;

        float4 s = make_float4(0.f, 0.f, 0.f, 0.f);
        int f = f0;
        #pragma unroll 1
        for (; f + 8 <= f1; f += 8) {
            float4 v0 = base[(size_t)(f + 0) * T4_SZ];
            float4 v1 = base[(size_t)(f + 1) * T4_SZ];
            float4 v2 = base[(size_t)(f + 2) * T4_SZ];
            float4 v3 = base[(size_t)(f + 3) * T4_SZ];
            float4 v4 = base[(size_t)(f + 4) * T4_SZ];
            float4 v5 = base[(size_t)(f + 5) * T4_SZ];
            float4 v6 = base[(size_t)(f + 6) * T4_SZ];
            float4 v7 = base[(size_t)(f + 7) * T4_SZ];
            s.x += ((v0.x + v1.x) + (v2.x + v3.x)) + ((v4.x + v5.x) + (v6.x + v7.x));
            s.y += ((v0.y + v1.y) + (v2.y + v3.y)) + ((v4.y + v5.y) + (v6.y + v7.y));
            s.z += ((v0.z + v1.z) + (v2.z + v3.z)) + ((v4.z + v5.z) + (v6.z + v7.z));
            s.w += ((v0.w + v1.w) + (v2.w + v3.w)) + ((v4.w + v5.w) + (v6.w + v7.w));
        }
        for (; f < f1; f++) {
            float4 v = base[(size_t)f * T4_SZ];
            s.x += v.x; s.y += v.y; s.z += v.z; s.w += v.w;
        }
        reinterpret_cast<float4*>(g_part)[((size_t)ch * B_SZ + b) * T4_SZ + t4] = s;
    }

    __threadfence();            // release partial writes
    __syncthreads();
    if (tid == 0)
        s_last = (atomicAdd(&g_cnt[b * NXT + xt], 1) == NCHUNK - 1);
    __syncthreads();
    if (!s_last) return;
    if (tid == 0) atomicExch(&g_cnt[b * NXT + xt], 0);   // replay-safe reset

    // ---------------- phase 2: segment scanner for (b, xt) -----------------
    const int tb = xt * SEGT;                        // segment start t
    const int L  = (T_SZ - tb) < SEGT ? (T_SZ - tb) : SEGT;

    // fold the 8 partials for this segment (32 KB from L2)
    for (int i = tid; i < L; i += THREADS) {
        float acc = 0.f;
        #pragma unroll
        for (int c = 0; c < NCHUNK; c++)
            acc += __ldcg(&g_part[((size_t)c * B_SZ + b) * T_SZ + tb + i]);
        s_stage[i] = acc * (1.0f / (float)F_SZ);
    }
    __syncthreads();

    // local pair-scan (identity for t >= L)
    float x[SEG2];
    float A = 1.0f, Bc = 0.0f;
    const int t0 = tid * SEG2;
    #pragma unroll
    for (int j = 0; j < SEG2; j++) {
        int t = t0 + j;
        if (t < L) {
            x[j] = s_stage[t];
            A  *= MOMENTUM;
            Bc  = MOMENTUM * Bc + ONE_MINUS_M * x[j];
        }
    }
    __syncthreads();

    sA[tid] = A; sB[tid] = Bc;
    __syncthreads();
    #pragma unroll
    for (int off = 1; off < THREADS; off <<= 1) {
        float a2 = sA[tid], b2 = sB[tid];
        float a1 = 1.0f, b1 = 0.0f;
        if (tid >= off) { a1 = sA[tid - off]; b1 = sB[tid - off]; }
        __syncthreads();
        sA[tid] = a2 * a1;
        sB[tid] = a2 * b1 + b2;
        __syncthreads();
    }

    float Ap = 1.0f, Bp = 0.0f;
    if (tid > 0) { Ap = sA[tid - 1]; Bp = sB[tid - 1]; }
    const float A_seg = sA[THREADS - 1];
    const float B_seg = sB[THREADS - 1];

    // scalar chain: acquire m_in, publish m_out IMMEDIATELY
    if (tid == 0) {
        float m_in;
        if (xt == 0) {
            m_in = running_mean[0];
        } else {
            const int pf = b * NXT + xt - 1;
            while (atomicAdd(&g_mflag[pf], 0) == 0) __nanosleep(32);
            __threadfence();
            m_in = __ldcg(&g_mval[pf]);
            atomicExch(&g_mflag[pf], 0);             // replay-safe reset
        }
        if (xt < NXT - 1) {
            const int mf = b * NXT + xt;
            g_mval[mf] = A_seg * m_in + B_seg;
            __threadfence();
            atomicExch(&g_mflag[mf], 1);
        }
        s_min = m_in;
    }
    __syncthreads();

    // parallel inv/mean for this segment
    float m = Ap * s_min + Bp;
    const float bi = bias[0];
    #pragma unroll
    for (int j = 0; j < SEG2; j++) {
        int t = t0 + j;
        if (t < L) {
            m = MOMENTUM * m + ONE_MINUS_M * x[j];
            float mwb = m + bi;
            s_stage[t]        = 1.0f / (mwb + EPS);
            s_stage[SEGT + t] = mwb;
        }
    }
    __syncthreads();

    float* invp  = g_inv + (size_t)b * T_SZ + tb;
    float* meanp = out_mean + (size_t)b * T_SZ + tb;
    for (int i = tid; i < L; i += THREADS) {
        invp[i]  = s_stage[i];
        meanp[i] = s_stage[SEGT + i];
    }
}

// ---------------------------------------------------------------------------
// kB: mag_norm = mag * inv[b,t]; 4 f-rows per iv load; reverse-b; write-
// through stores (measured best).  grid: (3, 65, 32), block 256.
// ---------------------------------------------------------------------------
__global__ __launch_bounds__(256)
void ema_kB(const float* __restrict__ mag,
            float* __restrict__ out_norm) {
    int t4 = blockIdx.x * blockDim.x + threadIdx.x;
    if (t4 >= T4_SZ) return;
    int f0 = blockIdx.y * 4;                 // 0,4,...,256
    int b  = (B_SZ - 1) - blockIdx.z;

    float4 iv = __ldca(reinterpret_cast<const float4*>(g_inv) + (size_t)b * T4_SZ + t4);

    const int nrows = (F_SZ - f0) < 4 ? (F_SZ - f0) : 4;
    size_t idx0 = ((size_t)b * F_SZ + f0) * T4_SZ + t4;

    float4 v[4];
    #pragma unroll
    for (int r = 0; r < 4; r++)
        if (r < nrows) v[r] = reinterpret_cast<const float4*>(mag)[idx0 + (size_t)r * T4_SZ];

    #pragma unroll
    for (int r = 0; r < 4; r++) {
        if (r < nrows) {
            v[r].x *= iv.x; v[r].y *= iv.y; v[r].z *= iv.z; v[r].w *= iv.w;
            __stwt(reinterpret_cast<float4*>(out_norm) + idx0 + (size_t)r * T4_SZ, v[r]);
        }
    }
}

// ---------------------------------------------------------------------------
extern "C" void kernel_launch(void* const* d_in, const int* in_sizes, int n_in,
                              void* d_out, int out_size) {
    const float* mag          = (const float*)d_in[0];
    const float* bias         = (const float*)d_in[1];
    const float* running_mean = (const float*)d_in[2];
    float* out = (float*)d_out;

    float* out_norm = out;                                // [B, F, T]
    float* out_mean = out + (size_t)B_SZ * F_SZ * T_SZ;   // [B, 1, T]

    {
        dim3 grid(NXT, NCHUNK, B_SZ);
        ema_kA<<<grid, THREADS>>>(mag, bias, running_mean, out_mean);
    }
    {
        dim3 grid(3, (F_SZ + 3) / 4, B_SZ);
        ema_kB<<<grid, 256>>>(mag, out_norm);
    }
}

// round 17
// speedup vs baseline: 1.1734x; 1.0025x over previous
#include <cuda_runtime.h>
#include <cuda_bf16.h>

#define B_SZ 32
#define F_SZ 257
#define T_SZ 3000
#define T4_SZ 750                 // float4 per row
#define NCHUNK 8                  // F-chunks: 7x32 + 33
#define NXT 3                     // t4 tiles of 256 -> t segments of 1024
#define THREADS 256
#define SEGT 1024                 // t per segment (last: 952)
#define MOMENTUM 0.99f
#define ONE_MINUS_M 0.01f
#define EPS 1e-8f
#define SEG2 4                    // 256*4 = 1024

// Scratch (static device globals; zero-initialized at load)
__device__ __align__(16) float g_part[NCHUNK * B_SZ * T_SZ];
__device__ __align__(16) float g_inv[B_SZ * T_SZ];
__device__ float g_mval[B_SZ * NXT];     // segment-exit EMA state
__device__ int   g_mflag[B_SZ * NXT];    // handoff flags (self-reset)
__device__ int   g_cnt[B_SZ * NXT];      // chunk arrivals per (b,xt) (self-reset)

// ---------------------------------------------------------------------------
// kA: column sums; last-arriver per (b, xt) becomes the segment scanner:
// fold 8 partials for its 1024-t range, local pair-scan, scalar chain across
// xt, then parallel inv/mean writeback.
// grid: (NXT, NCHUNK, B_SZ) = 768 blocks, 256 threads.
// ---------------------------------------------------------------------------
__global__ __launch_bounds__(THREADS)
void ema_kA(const float* __restrict__ mag,
            const float* __restrict__ bias,
            const float* __restrict__ running_mean,
            float* __restrict__ out_mean) {
    __shared__ float s_stage[2 * SEGT];     // x, then inv|mean
    __shared__ float sA[THREADS], sB[THREADS];
    __shared__ int s_last;
    __shared__ float s_min;

    const int tid = threadIdx.x;
    const int xt  = blockIdx.x;
    const int ch  = blockIdx.y;
    const int b   = blockIdx.z;
    const int t4  = xt * THREADS + tid;

    // ---------------- phase 1: column sums for (b, ch, xt) -----------------
    if (t4 < T4_SZ) {
        int f0 = ch * 32;
        int f1 = (ch == NCHUNK - 1) ? F_SZ : f0 + 32;

        const float4* base = reinterpret_cast<const float4*>(mag)
                           + (size_t)b * F_SZ * T4_SZ + t4;

        float4 s = make_float4(0.f, 0.f, 0.f, 0.f);
        int f = f0;
        #pragma unroll 1
        for (; f + 8 <= f1; f += 8) {
            float4 v0 = base[(size_t)(f + 0) * T4_SZ];
            float4 v1 = base[(size_t)(f + 1) * T4_SZ];
            float4 v2 = base[(size_t)(f + 2) * T4_SZ];
            float4 v3 = base[(size_t)(f + 3) * T4_SZ];
            float4 v4 = base[(size_t)(f + 4) * T4_SZ];
            float4 v5 = base[(size_t)(f + 5) * T4_SZ];
            float4 v6 = base[(size_t)(f + 6) * T4_SZ];
            float4 v7 = base[(size_t)(f + 7) * T4_SZ];
            s.x += ((v0.x + v1.x) + (v2.x + v3.x)) + ((v4.x + v5.x) + (v6.x + v7.x));
            s.y += ((v0.y + v1.y) + (v2.y + v3.y)) + ((v4.y + v5.y) + (v6.y + v7.y));
            s.z += ((v0.z + v1.z) + (v2.z + v3.z)) + ((v4.z + v5.z) + (v6.z + v7.z));
            s.w += ((v0.w + v1.w) + (v2.w + v3.w)) + ((v4.w + v5.w) + (v6.w + v7.w));
        }
        for (; f < f1; f++) {
            float4 v = base[(size_t)f * T4_SZ];
            s.x += v.x; s.y += v.y; s.z += v.z; s.w += v.w;
        }
        reinterpret_cast<float4*>(g_part)[((size_t)ch * B_SZ + b) * T4_SZ + t4] = s;
    }

    __threadfence();            // release partial writes
    __syncthreads();
    if (tid == 0)
        s_last = (atomicAdd(&g_cnt[b * NXT + xt], 1) == NCHUNK - 1);
    __syncthreads();
    if (!s_last) return;
    if (tid == 0) atomicExch(&g_cnt[b * NXT + xt], 0);   // replay-safe reset

    // ---------------- phase 2: segment scanner for (b, xt) -----------------
    const float bi = bias[0];                        // hoisted off critical path
    const int tb = xt * SEGT;                        // segment start t
    const int L  = (T_SZ - tb) < SEGT ? (T_SZ - tb) : SEGT;

    // fold the 8 partials for this segment (32 KB from L2)
    for (int i = tid; i < L; i += THREADS) {
        float acc = 0.f;
        #pragma unroll
        for (int c = 0; c < NCHUNK; c++)
            acc += __ldcg(&g_part[((size_t)c * B_SZ + b) * T_SZ + tb + i]);
        s_stage[i] = acc * (1.0f / (float)F_SZ);
    }
    __syncthreads();

    // local pair-scan (identity for t >= L)
    float x[SEG2];
    float A = 1.0f, Bc = 0.0f;
    const int t0 = tid * SEG2;
    #pragma unroll
    for (int j = 0; j < SEG2; j++) {
        int t = t0 + j;
        if (t < L) {
            x[j] = s_stage[t];
            A  *= MOMENTUM;
            Bc  = MOMENTUM * Bc + ONE_MINUS_M * x[j];
        }
    }
    __syncthreads();

    sA[tid] = A; sB[tid] = Bc;
    __syncthreads();
    #pragma unroll
    for (int off = 1; off < THREADS; off <<= 1) {
        float a2 = sA[tid], b2 = sB[tid];
        float a1 = 1.0f, b1 = 0.0f;
        if (tid >= off) { a1 = sA[tid - off]; b1 = sB[tid - off]; }
        __syncthreads();
        sA[tid] = a2 * a1;
        sB[tid] = a2 * b1 + b2;
        __syncthreads();
    }

    float Ap = 1.0f, Bp = 0.0f;
    if (tid > 0) { Ap = sA[tid - 1]; Bp = sB[tid - 1]; }
    const float A_seg = sA[THREADS - 1];
    const float B_seg = sB[THREADS - 1];

    // scalar chain: acquire m_in, publish m_out IMMEDIATELY
    if (tid == 0) {
        float m_in;
        if (xt == 0) {
            m_in = running_mean[0];
        } else {
            const int pf = b * NXT + xt - 1;
            while (atomicAdd(&g_mflag[pf], 0) == 0) __nanosleep(32);
            __threadfence();
            m_in = __ldcg(&g_mval[pf]);
            atomicExch(&g_mflag[pf], 0);             // replay-safe reset
        }
        if (xt < NXT - 1) {
            const int mf = b * NXT + xt;
            g_mval[mf] = A_seg * m_in + B_seg;
            __threadfence();
            atomicExch(&g_mflag[mf], 1);
        }
        s_min = m_in;
    }
    __syncthreads();

    // parallel inv/mean for this segment
    float m = Ap * s_min + Bp;
    #pragma unroll
    for (int j = 0; j < SEG2; j++) {
        int t = t0 + j;
        if (t < L) {
            m = MOMENTUM * m + ONE_MINUS_M * x[j];
            float mwb = m + bi;
            s_stage[t]        = 1.0f / (mwb + EPS);
            s_stage[SEGT + t] = mwb;
        }
    }
    __syncthreads();

    float* invp  = g_inv + (size_t)b * T_SZ + tb;
    float* meanp = out_mean + (size_t)b * T_SZ + tb;
    for (int i = tid; i < L; i += THREADS) {
        invp[i]  = s_stage[i];
        meanp[i] = s_stage[SEGT + i];
    }
}

// ---------------------------------------------------------------------------
// kB: mag_norm = mag * inv[b,t]; 8 f-rows per iv load (half the inv traffic
// of the 4-row version, 8-deep load batch); reverse-b; write-through stores.
// grid: (3, 33, 32), block 256.
// ---------------------------------------------------------------------------
__global__ __launch_bounds__(256)
void ema_kB(const float* __restrict__ mag,
            float* __restrict__ out_norm) {
    int t4 = blockIdx.x * blockDim.x + threadIdx.x;
    if (t4 >= T4_SZ) return;
    int f0 = blockIdx.y * 8;                 // 0,8,...,256
    int b  = (B_SZ - 1) - blockIdx.z;

    float4 iv = __ldca(reinterpret_cast<const float4*>(g_inv) + (size_t)b * T4_SZ + t4);

    const int nrows = (F_SZ - f0) < 8 ? (F_SZ - f0) : 8;
    size_t idx0 = ((size_t)b * F_SZ + f0) * T4_SZ + t4;

    float4 v[8];
    #pragma unroll
    for (int r = 0; r < 8; r++)
        if (r < nrows) v[r] = reinterpret_cast<const float4*>(mag)[idx0 + (size_t)r * T4_SZ];

    #pragma unroll
    for (int r = 0; r < 8; r++) {
        if (r < nrows) {
            v[r].x *= iv.x; v[r].y *= iv.y; v[r].z *= iv.z; v[r].w *= iv.w;
            __stwt(reinterpret_cast<float4*>(out_norm) + idx0 + (size_t)r * T4_SZ, v[r]);
        }
    }
}

// ---------------------------------------------------------------------------
extern "C" void kernel_launch(void* const* d_in, const int* in_sizes, int n_in,
                              void* d_out, int out_size) {
    const float* mag          = (const float*)d_in[0];
    const float* bias         = (const float*)d_in[1];
    const float* running_mean = (const float*)d_in[2];
    float* out = (float*)d_out;

    float* out_norm = out;                                // [B, F, T]
    float* out_mean = out + (size_t)B_SZ * F_SZ * T_SZ;   // [B, 1, T]

    {
        dim3 grid(NXT, NCHUNK, B_SZ);
        ema_kA<<<grid, THREADS>>>(mag, bias, running_mean, out_mean);
    }
    {
        dim3 grid(3, (F_SZ + 7) / 8, B_SZ);
        ema_kB<<<grid, 256>>>(mag, out_norm);
    }
}